// round 1
// baseline (speedup 1.0000x reference)
#include <cuda_runtime.h>

// NN_16_1_Pooling: x[16,64,224,224] f32 -> per 2x2 patch MLP (4->16 relu ->1)
// -> out[16,64,112,112] f32.
//
// Strategy: one thread processes a horizontal PAIR of patches per grid-stride
// iteration (two float4 row loads cover both patches). Hidden dim (16) is
// computed in packed f32x2 pairs via fma.rn.f32x2 -> 32 FFMA2 per patch
// instead of 64 FFMA. Weights live in registers (97 regs), loaded once per
// thread and amortized over ~25 iterations.

typedef unsigned long long u64;

#define B_ 16
#define C_ 64
#define H_ 224
#define W_ 224
#define NH 112
#define NW 112
#define PAIRS_PER_ROW 56                       // NW/2
#define NROWS (B_ * C_ * NH)                   // 114688
#define NPAIRS (NROWS * PAIRS_PER_ROW)         // 6,422,528

__device__ __forceinline__ u64 pk2(float lo, float hi) {
    u64 r;
    asm("mov.b64 %0, {%1, %2};" : "=l"(r) : "f"(lo), "f"(hi));
    return r;
}
__device__ __forceinline__ u64 fma2(u64 a, u64 b, u64 c) {
    u64 d;
    asm("fma.rn.f32x2 %0, %1, %2, %3;" : "=l"(d) : "l"(a), "l"(b), "l"(c));
    return d;
}
__device__ __forceinline__ float2 upk(u64 v) {
    float lo, hi;
    asm("mov.b64 {%0, %1}, %2;" : "=f"(lo), "=f"(hi) : "l"(v));
    return make_float2(lo, hi);
}

__global__ __launch_bounds__(128)
void mlp_pool_kernel(const float* __restrict__ x,
                     const float* __restrict__ W1,   // [16,4]
                     const float* __restrict__ b1,   // [16]
                     const float* __restrict__ W2,   // [1,16]
                     const float* __restrict__ b2,   // [1]
                     float* __restrict__ out)
{
    // ---- Load weights into registers, packed across hidden pairs ----
    u64 w1p[8][4];   // {W1[2hp][k], W1[2hp+1][k]}
    u64 b1p[8];
    float w2[16];
    #pragma unroll
    for (int hp = 0; hp < 8; hp++) {
        #pragma unroll
        for (int k = 0; k < 4; k++)
            w1p[hp][k] = pk2(__ldg(W1 + (2 * hp) * 4 + k),
                             __ldg(W1 + (2 * hp + 1) * 4 + k));
        b1p[hp] = pk2(__ldg(b1 + 2 * hp), __ldg(b1 + 2 * hp + 1));
    }
    #pragma unroll
    for (int h = 0; h < 16; h++) w2[h] = __ldg(W2 + h);
    const float bias2 = __ldg(b2);

    const int stride = gridDim.x * blockDim.x;
    for (int p = blockIdx.x * blockDim.x + threadIdx.x; p < NPAIRS; p += stride) {
        const int j = p % PAIRS_PER_ROW;       // pair index along width
        const int r = p / PAIRS_PER_ROW;       // global row: ((b*C + c)*NH + i)
        const int chan = r / NH;
        const int i = r - chan * NH;

        // input: rows 2i and 2i+1, cols [4j, 4j+3]
        const float4* row0 = (const float4*)(x + (long long)chan * (H_ * W_)
                                               + (2 * i) * W_ + 4 * j);
        const float4 t = __ldg(row0);           // top row of both patches
        const float4 u = __ldg(row0 + W_ / 4);  // bottom row (224 floats = 56 float4)

        float o[2];
        #pragma unroll
        for (int pa = 0; pa < 2; pa++) {
            // patch elements in row-major (kh,kw) order
            const float k0 = pa ? t.z : t.x;
            const float k1 = pa ? t.w : t.y;
            const float k2 = pa ? u.z : u.x;
            const float k3 = pa ? u.w : u.y;
            const u64 x0 = pk2(k0, k0);
            const u64 x1 = pk2(k1, k1);
            const u64 x2 = pk2(k2, k2);
            const u64 x3 = pk2(k3, k3);

            float acc = bias2;
            #pragma unroll
            for (int hp = 0; hp < 8; hp++) {
                u64 h2 = b1p[hp];
                h2 = fma2(w1p[hp][0], x0, h2);
                h2 = fma2(w1p[hp][1], x1, h2);
                h2 = fma2(w1p[hp][2], x2, h2);
                h2 = fma2(w1p[hp][3], x3, h2);
                const float2 hv = upk(h2);
                acc = fmaf(w2[2 * hp],     fmaxf(hv.x, 0.0f), acc);
                acc = fmaf(w2[2 * hp + 1], fmaxf(hv.y, 0.0f), acc);
            }
            o[pa] = acc;
        }

        // two adjacent outputs, 8B-aligned
        float2* op = (float2*)(out + (long long)r * NW + 2 * j);
        *op = make_float2(o[0], o[1]);
    }
}

extern "C" void kernel_launch(void* const* d_in, const int* in_sizes, int n_in,
                              void* d_out, int out_size)
{
    const float* x  = (const float*)d_in[0];
    const float* W1 = (const float*)d_in[1];
    const float* b1 = (const float*)d_in[2];
    const float* W2 = (const float*)d_in[3];
    const float* b2 = (const float*)d_in[4];
    float* out = (float*)d_out;

    // 148 SMs * 12 blocks of 128 threads: ~25 grid-stride iterations/thread,
    // weight-load cost amortized, full coalescing.
    const int blocks = 148 * 12;
    mlp_pool_kernel<<<blocks, 128>>>(x, W1, b1, W2, b2, out);
}

// round 2
// speedup vs baseline: 1.2514x; 1.2514x over previous
#include <cuda_runtime.h>

// NN_16_1_Pooling: x[16,64,224,224] f32 -> per 2x2 patch MLP (4->16 relu ->1)
// -> out[16,64,112,112] f32.
//
// R2: MLP-starved in R1 (16 warps x 2 loads = 16KB outstanding -> 3TB/s).
// Now each thread loads 8 float4 (4 row-pairs = 8 patches) per iteration,
// issued back-to-back: MLP=8. Hidden layer AND output layer both run as
// packed fma.rn.f32x2. Weights stay in registers (97), occupancy capped at
// 3 CTAs/SM via launch_bounds; outstanding bytes/SM = 12 warps*8*512B = 48KB.

typedef unsigned long long u64;

#define CH_ 1024                    // b*c planes (16*64)
#define H_ 224
#define W_ 224
#define W4 56                       // W_/4 in float4 units
#define NH 112
#define NW 112
#define JP 56                       // pair-columns per output row
#define QUADS 28                    // NH/4
#define NIT (CH_ * QUADS * JP)      // 1,605,632 iterations

__device__ __forceinline__ u64 pk2(float lo, float hi) {
    u64 r;
    asm("mov.b64 %0, {%1, %2};" : "=l"(r) : "f"(lo), "f"(hi));
    return r;
}
__device__ __forceinline__ u64 fma2(u64 a, u64 b, u64 c) {
    u64 d;
    asm("fma.rn.f32x2 %0, %1, %2, %3;" : "=l"(d) : "l"(a), "l"(b), "l"(c));
    return d;
}
__device__ __forceinline__ float2 upk(u64 v) {
    float lo, hi;
    asm("mov.b64 {%0, %1}, %2;" : "=f"(lo), "=f"(hi) : "l"(v));
    return make_float2(lo, hi);
}

__global__ __launch_bounds__(128, 3)
void mlp_pool_kernel(const float* __restrict__ x,
                     const float* __restrict__ W1,   // [16,4]
                     const float* __restrict__ b1,   // [16]
                     const float* __restrict__ W2,   // [1,16]
                     const float* __restrict__ b2,   // [1]
                     float* __restrict__ out)
{
    // ---- Weights in registers, packed across hidden pairs (97 regs) ----
    u64 w1p[8][4];   // {W1[2hp][k], W1[2hp+1][k]}
    u64 b1p[8];
    u64 w2p[8];      // {W2[2hp], W2[2hp+1]}
    #pragma unroll
    for (int hp = 0; hp < 8; hp++) {
        #pragma unroll
        for (int k = 0; k < 4; k++)
            w1p[hp][k] = pk2(__ldg(W1 + (2 * hp) * 4 + k),
                             __ldg(W1 + (2 * hp + 1) * 4 + k));
        b1p[hp] = pk2(__ldg(b1 + 2 * hp), __ldg(b1 + 2 * hp + 1));
        w2p[hp] = pk2(__ldg(W2 + 2 * hp), __ldg(W2 + 2 * hp + 1));
    }
    const float bias2 = __ldg(b2);

    const int stride = gridDim.x * blockDim.x;
    for (int p = blockIdx.x * blockDim.x + threadIdx.x; p < NIT; p += stride) {
        const int j = p % JP;                 // float4 column (pair of patches)
        const int t = p / JP;
        const int chan = t / QUADS;
        const int q = t - chan * QUADS;       // output-row quad within plane

        // ---- 8 coalesced float4 loads, issued back-to-back (MLP=8) ----
        const float4* base = (const float4*)x
                           + (long long)chan * (H_ * W4) + (q * 8) * W4 + j;
        float4 v[8];
        #pragma unroll
        for (int r = 0; r < 8; r++) v[r] = __ldg(base + r * W4);

        // ---- 4 row-pairs x 2 patches each ----
        #pragma unroll
        for (int rp = 0; rp < 4; rp++) {
            const float4 tt = v[2 * rp];
            const float4 uu = v[2 * rp + 1];
            float o2[2];
            #pragma unroll
            for (int pa = 0; pa < 2; pa++) {
                const float k0 = pa ? tt.z : tt.x;
                const float k1 = pa ? tt.w : tt.y;
                const float k2 = pa ? uu.z : uu.x;
                const float k3 = pa ? uu.w : uu.y;
                const u64 x0 = pk2(k0, k0);
                const u64 x1 = pk2(k1, k1);
                const u64 x2 = pk2(k2, k2);
                const u64 x3 = pk2(k3, k3);

                u64 accp = 0ull;              // packed {acc_even, acc_odd}
                #pragma unroll
                for (int hp = 0; hp < 8; hp++) {
                    u64 h2 = b1p[hp];
                    h2 = fma2(w1p[hp][0], x0, h2);
                    h2 = fma2(w1p[hp][1], x1, h2);
                    h2 = fma2(w1p[hp][2], x2, h2);
                    h2 = fma2(w1p[hp][3], x3, h2);
                    const float2 hv = upk(h2);
                    const u64 rl = pk2(fmaxf(hv.x, 0.0f), fmaxf(hv.y, 0.0f));
                    accp = fma2(w2p[hp], rl, accp);
                }
                const float2 a = upk(accp);
                o2[pa] = a.x + a.y + bias2;
            }
            // output row i = q*4 + rp, cols [2j, 2j+1]
            float2* op = (float2*)(out
                         + ((long long)chan * NH + q * 4 + rp) * NW + 2 * j);
            *op = make_float2(o2[0], o2[1]);
        }
    }
}

extern "C" void kernel_launch(void* const* d_in, const int* in_sizes, int n_in,
                              void* d_out, int out_size)
{
    const float* x  = (const float*)d_in[0];
    const float* W1 = (const float*)d_in[1];
    const float* b1 = (const float*)d_in[2];
    const float* W2 = (const float*)d_in[3];
    const float* b2 = (const float*)d_in[4];
    float* out = (float*)d_out;

    // Single wave: 148 SMs * 3 resident CTAs, ~28 grid-stride iters/thread.
    const int blocks = 148 * 3;
    mlp_pool_kernel<<<blocks, 128>>>(x, W1, b1, W2, b2, out);
}

// round 3
// speedup vs baseline: 1.3127x; 1.0490x over previous
#include <cuda_runtime.h>

// NN_16_1_Pooling: x[16,64,224,224] f32 -> per 2x2 patch MLP (4->16 relu ->1)
// -> out[16,64,112,112] f32.
//
// R3: R2 was latency-bound (DRAM 47%, issue 38%, nothing saturated) because
// loads were only in flight at iteration start. Now software-pipelined:
// iteration n+1's 4 float4 loads are issued BEFORE iteration n's compute
// (ping-pong register buffers, manual 2x unroll). 12 warps/SM keep ~24KB
// continuously outstanding -> memory latency fully hidden behind fma work.

typedef unsigned long long u64;

#define CH_ 1024                    // b*c planes (16*64)
#define H_ 224
#define W4 56                       // input row in float4 units
#define NH 112
#define NW 112
#define JP 56                       // float4 columns per row (pair of patches)
#define DQ 56                       // output double-rows per plane (NH/2)
#define NIT (CH_ * DQ * JP)         // 3,211,264 iterations (4 patches each)

__device__ __forceinline__ u64 pk2(float lo, float hi) {
    u64 r;
    asm("mov.b64 %0, {%1, %2};" : "=l"(r) : "f"(lo), "f"(hi));
    return r;
}
__device__ __forceinline__ u64 fma2(u64 a, u64 b, u64 c) {
    u64 d;
    asm("fma.rn.f32x2 %0, %1, %2, %3;" : "=l"(d) : "l"(a), "l"(b), "l"(c));
    return d;
}
__device__ __forceinline__ float2 upk(u64 v) {
    float lo, hi;
    asm("mov.b64 {%0, %1}, %2;" : "=f"(lo), "=f"(hi) : "l"(v));
    return make_float2(lo, hi);
}

struct W {
    u64 w1p[8][4];   // {W1[2hp][k], W1[2hp+1][k]}
    u64 b1p[8];
    u64 w2p[8];
    float bias2;
};

// 4 coalesced float4 loads for iteration p (2 input row-pairs, 4 patches)
__device__ __forceinline__ void load4(float4* v, const float* __restrict__ x, int p) {
    const int j = p % JP;
    const int t = p / JP;
    const int chan = t / DQ;
    const int q = t - chan * DQ;      // output double-row -> input rows 4q..4q+3
    const float4* base = (const float4*)x + (long long)chan * (H_ * W4)
                       + (q * 4) * W4 + j;
    v[0] = __ldg(base);
    v[1] = __ldg(base + W4);
    v[2] = __ldg(base + 2 * W4);
    v[3] = __ldg(base + 3 * W4);
}

__device__ __forceinline__ void compute_store(const float4* v, const W& w,
                                              float* __restrict__ out, int p) {
    const int j = p % JP;
    const int t = p / JP;
    const int chan = t / DQ;
    const int q = t - chan * DQ;

    #pragma unroll
    for (int rp = 0; rp < 2; rp++) {
        const float4 tt = v[2 * rp];
        const float4 uu = v[2 * rp + 1];
        float o2[2];
        #pragma unroll
        for (int pa = 0; pa < 2; pa++) {
            const float k0 = pa ? tt.z : tt.x;
            const float k1 = pa ? tt.w : tt.y;
            const float k2 = pa ? uu.z : uu.x;
            const float k3 = pa ? uu.w : uu.y;
            const u64 x0 = pk2(k0, k0);
            const u64 x1 = pk2(k1, k1);
            const u64 x2 = pk2(k2, k2);
            const u64 x3 = pk2(k3, k3);

            u64 accp = 0ull;
            #pragma unroll
            for (int hp = 0; hp < 8; hp++) {
                u64 h2 = w.b1p[hp];
                h2 = fma2(w.w1p[hp][0], x0, h2);
                h2 = fma2(w.w1p[hp][1], x1, h2);
                h2 = fma2(w.w1p[hp][2], x2, h2);
                h2 = fma2(w.w1p[hp][3], x3, h2);
                const float2 hv = upk(h2);
                const u64 rl = pk2(fmaxf(hv.x, 0.0f), fmaxf(hv.y, 0.0f));
                accp = fma2(w.w2p[hp], rl, accp);
            }
            const float2 a = upk(accp);
            o2[pa] = a.x + a.y + w.bias2;
        }
        float2* op = (float2*)(out + ((long long)chan * NH + q * 2 + rp) * NW + 2 * j);
        *op = make_float2(o2[0], o2[1]);
    }
}

__global__ __launch_bounds__(128, 3)
void mlp_pool_kernel(const float* __restrict__ x,
                     const float* __restrict__ W1,   // [16,4]
                     const float* __restrict__ b1,   // [16]
                     const float* __restrict__ W2,   // [1,16]
                     const float* __restrict__ b2,   // [1]
                     float* __restrict__ out)
{
    W w;
    #pragma unroll
    for (int hp = 0; hp < 8; hp++) {
        #pragma unroll
        for (int k = 0; k < 4; k++)
            w.w1p[hp][k] = pk2(__ldg(W1 + (2 * hp) * 4 + k),
                               __ldg(W1 + (2 * hp + 1) * 4 + k));
        w.b1p[hp] = pk2(__ldg(b1 + 2 * hp), __ldg(b1 + 2 * hp + 1));
        w.w2p[hp] = pk2(__ldg(W2 + 2 * hp), __ldg(W2 + 2 * hp + 1));
    }
    w.bias2 = __ldg(b2);

    const int stride = gridDim.x * blockDim.x;
    int p = blockIdx.x * blockDim.x + threadIdx.x;
    if (p >= NIT) return;

    float4 va[4], vb[4];
    load4(va, x, p);

    // Ping-pong pipeline: prefetch next iteration's loads before computing
    // the current one. Manual 2x unroll keeps buffers in fixed registers.
    for (;;) {
        int pn = p + stride;
        if (pn < NIT) load4(vb, x, pn);
        compute_store(va, w, out, p);
        if (pn >= NIT) break;
        p = pn;

        pn = p + stride;
        if (pn < NIT) load4(va, x, pn);
        compute_store(vb, w, out, p);
        if (pn >= NIT) break;
        p = pn;
    }
}

extern "C" void kernel_launch(void* const* d_in, const int* in_sizes, int n_in,
                              void* d_out, int out_size)
{
    const float* x  = (const float*)d_in[0];
    const float* W1 = (const float*)d_in[1];
    const float* b1 = (const float*)d_in[2];
    const float* W2 = (const float*)d_in[3];
    const float* b2 = (const float*)d_in[4];
    float* out = (float*)d_out;

    // Single wave: 148 SMs * 3 resident CTAs of 128 threads.
    const int blocks = 148 * 3;
    mlp_pool_kernel<<<blocks, 128>>>(x, W1, b1, W2, b2, out);
}

// round 4
// speedup vs baseline: 1.5624x; 1.1902x over previous
#include <cuda_runtime.h>

// NN_16_1_Pooling: x[16,64,224,224] f32 -> per 2x2 patch MLP (4->16 relu ->1)
// -> out[16,64,112,112] f32.
//
// R4: DRAM-delivery-limited at 49% because only 24KB/SM in flight and ~40
// instrs/iter of div/mod index math. Fix:
//  * exact-stride mapping: 56448 threads = 56(j) x 56(q) x 18(chan0); the
//    grid stride keeps j,q FIXED; only chan += 18 -> loop is pure pointer
//    increments (no div/mod anywhere in the loop).
//  * 3-deep prefetch ring (3 x 4 float4) -> 36KB continuously outstanding/SM.
//  * bias2 folded into packed accumulator init.

typedef unsigned long long u64;

#define W4 56                        // input row pitch in float4
#define IN_STEP (18 * 224 * 56)      // 18 planes, in float4 units
#define OUT_STEP (18 * 112 * 56)     // 18 planes, in float2 units
#define OUT_PITCH2 56                // output row pitch in float2

__device__ __forceinline__ u64 pk2(float lo, float hi) {
    u64 r;
    asm("mov.b64 %0, {%1, %2};" : "=l"(r) : "f"(lo), "f"(hi));
    return r;
}
__device__ __forceinline__ u64 fma2(u64 a, u64 b, u64 c) {
    u64 d;
    asm("fma.rn.f32x2 %0, %1, %2, %3;" : "=l"(d) : "l"(a), "l"(b), "l"(c));
    return d;
}
__device__ __forceinline__ float2 upk(u64 v) {
    float lo, hi;
    asm("mov.b64 {%0, %1}, %2;" : "=f"(lo), "=f"(hi) : "l"(v));
    return make_float2(lo, hi);
}

struct Wts {
    u64 w1p[8][4];   // {W1[2hp][k], W1[2hp+1][k]}
    u64 b1p[8];
    u64 w2p[8];
    float bias2;
};

__device__ __forceinline__ void load4(float4* v, const float4* __restrict__ p) {
    v[0] = __ldg(p);
    v[1] = __ldg(p + W4);
    v[2] = __ldg(p + 2 * W4);
    v[3] = __ldg(p + 3 * W4);
}

__device__ __forceinline__ void compute_store(const float4* v, const Wts& w,
                                              float2* __restrict__ op) {
    #pragma unroll
    for (int rp = 0; rp < 2; rp++) {
        const float4 tt = v[2 * rp];
        const float4 uu = v[2 * rp + 1];
        float o2[2];
        #pragma unroll
        for (int pa = 0; pa < 2; pa++) {
            const float k0 = pa ? tt.z : tt.x;
            const float k1 = pa ? tt.w : tt.y;
            const float k2 = pa ? uu.z : uu.x;
            const float k3 = pa ? uu.w : uu.y;
            const u64 x0 = pk2(k0, k0);
            const u64 x1 = pk2(k1, k1);
            const u64 x2 = pk2(k2, k2);
            const u64 x3 = pk2(k3, k3);

            u64 accp = pk2(w.bias2, 0.0f);   // fold final bias into lane 0
            #pragma unroll
            for (int hp = 0; hp < 8; hp++) {
                u64 h2 = w.b1p[hp];
                h2 = fma2(w.w1p[hp][0], x0, h2);
                h2 = fma2(w.w1p[hp][1], x1, h2);
                h2 = fma2(w.w1p[hp][2], x2, h2);
                h2 = fma2(w.w1p[hp][3], x3, h2);
                const float2 hv = upk(h2);
                const u64 rl = pk2(fmaxf(hv.x, 0.0f), fmaxf(hv.y, 0.0f));
                accp = fma2(w.w2p[hp], rl, accp);
            }
            const float2 a = upk(accp);
            o2[pa] = a.x + a.y;
        }
        op[rp * OUT_PITCH2] = make_float2(o2[0], o2[1]);
    }
}

__global__ __launch_bounds__(128, 3)
void mlp_pool_kernel(const float* __restrict__ x,
                     const float* __restrict__ W1,   // [16,4]
                     const float* __restrict__ b1,   // [16]
                     const float* __restrict__ W2,   // [1,16]
                     const float* __restrict__ b2,   // [1]
                     float* __restrict__ out)
{
    Wts w;
    #pragma unroll
    for (int hp = 0; hp < 8; hp++) {
        #pragma unroll
        for (int k = 0; k < 4; k++)
            w.w1p[hp][k] = pk2(__ldg(W1 + (2 * hp) * 4 + k),
                               __ldg(W1 + (2 * hp + 1) * 4 + k));
        w.b1p[hp] = pk2(__ldg(b1 + 2 * hp), __ldg(b1 + 2 * hp + 1));
        w.w2p[hp] = pk2(__ldg(W2 + 2 * hp), __ldg(W2 + 2 * hp + 1));
    }
    w.bias2 = __ldg(b2);

    // tid -> (j fixed, q fixed, chan0); chan walks chan0, chan0+18, ...
    const int tid = blockIdx.x * blockDim.x + threadIdx.x;   // < 56448
    const int j = tid % 56;
    const int t = tid / 56;
    const int q = t % 56;          // output double-row within plane
    const int chan0 = t / 56;      // 0..17
    const int n = (1023 - chan0) / 18 + 1;   // 56 or 57 iterations

    const float4* ip = (const float4*)x
                     + (long long)chan0 * (224 * 56) + (4 * q) * W4 + j;
    float2* op = (float2*)out
               + (long long)chan0 * (112 * 56) + (2 * q) * OUT_PITCH2 + j;

    float4 va[4], vb[4], vc[4];

    // Prologue: 2 stages in flight (n >= 2 always).
    load4(va, ip); ip += IN_STEP;
    load4(vb, ip); ip += IN_STEP;

    int i = 0;
    for (;;) {
        if (i + 2 < n) { load4(vc, ip); ip += IN_STEP; }
        compute_store(va, w, op); op += OUT_STEP;
        if (++i >= n) break;

        if (i + 2 < n) { load4(va, ip); ip += IN_STEP; }
        compute_store(vb, w, op); op += OUT_STEP;
        if (++i >= n) break;

        if (i + 2 < n) { load4(vb, ip); ip += IN_STEP; }
        compute_store(vc, w, op); op += OUT_STEP;
        if (++i >= n) break;
    }
}

extern "C" void kernel_launch(void* const* d_in, const int* in_sizes, int n_in,
                              void* d_out, int out_size)
{
    const float* x  = (const float*)d_in[0];
    const float* W1 = (const float*)d_in[1];
    const float* b1 = (const float*)d_in[2];
    const float* W2 = (const float*)d_in[3];
    const float* b2 = (const float*)d_in[4];
    float* out = (float*)d_out;

    // 441 blocks x 128 threads = 56448 threads = 56 * 56 * 18 (exact).
    mlp_pool_kernel<<<441, 128>>>(x, W1, b1, W2, b2, out);
}